// round 11
// baseline (speedup 1.0000x reference)
#include <cuda_runtime.h>
#include <cuda_fp16.h>
#include <math.h>

// Problem constants
#define B_N   4096
#define M_N   256
#define D_N   256
#define TAU_F       0.2f
#define INV2TAU_F   2.5f
#define TOPO_F      0.5f
#define LEN_C_F     0.01f
#define SP_C_F      0.001f
#define NEIGH_LOG2  (-0.18033688011112042f)   // -log2(e)/8
#define NPAIR (B_N / 2)                       // 2048 row pairs
#define FULLM 0xffffffffu

// ---------------- device scratch ----------------
__device__ float g_dist[B_N * M_N];
__device__ float g_protosq[M_N * M_N];
__device__ float g_factor[M_N];
__device__ float g_wsq[M_N];
__device__ float g_rowp[M_N];
__device__ float g_rowpd[M_N];
__device__ float g_partial[NPAIR];
__device__ int   g_ctr;

// ---------------- helpers ----------------
__device__ __forceinline__ unsigned h2tanh(unsigned x) {
    unsigned y;
    asm("tanh.approx.f16x2 %0, %1;" : "=r"(y) : "r"(x));
    return y;
}
__device__ __forceinline__ unsigned h2sub(unsigned a, unsigned b) {
    unsigned r;
    asm("sub.f16x2 %0, %1, %2;" : "=r"(r) : "r"(a), "r"(b));
    return r;
}
__device__ __forceinline__ unsigned h2add(unsigned a, unsigned b) {
    unsigned r;
    asm("add.f16x2 %0, %1, %2;" : "=r"(r) : "r"(a), "r"(b));
    return r;
}
__device__ __forceinline__ void h2acc(unsigned h2, float& a, float& b) {
    __half2 h = *reinterpret_cast<__half2*>(&h2);
    float2 f = __half22float2(h);
    a += f.x; b += f.y;
}
__device__ __forceinline__ void h2accneg(unsigned h2, float& a, float& b) {
    __half2 h = *reinterpret_cast<__half2*>(&h2);
    float2 f = __half22float2(h);
    a -= f.x; b -= f.y;
}

__device__ __forceinline__ float block_reduce_256(float v, float* sh) {
    int t = threadIdx.x;
    sh[t] = v;
    __syncthreads();
    #pragma unroll
    for (int s = 128; s > 0; s >>= 1) {
        if (t < s) sh[t] += sh[t + s];
        __syncthreads();
    }
    float r = sh[0];
    __syncthreads();
    return r;
}

// ---------------- proto pairwise squared distances (16 blocks) ----------
__global__ __launch_bounds__(256) void sqdist_proto(const float* __restrict__ W) {
    __shared__ __align__(16) float xs[16 * 256];
    __shared__ float ws[16 * 260];

    const int tid = threadIdx.x;
    const int r0  = blockIdx.x * 16;

    if (blockIdx.x == 0 && tid == 0) g_ctr = 0;   // reset last-block counter

    const float* Ab = W + r0 * D_N;
    #pragma unroll
    for (int k = 0; k < 16; ++k) xs[k * 256 + tid] = Ab[k * 256 + tid];

    float acc[16];
    #pragma unroll
    for (int r = 0; r < 16; ++r) acc[r] = 0.0f;

    for (int c = 0; c < 16; ++c) {
        __syncthreads();
        #pragma unroll
        for (int k = 0; k < 16; ++k) {
            int mm = k * 16 + (tid >> 4), dc = tid & 15;
            ws[dc * 260 + mm] = W[mm * 256 + c * 16 + dc];
        }
        __syncthreads();
        #pragma unroll
        for (int g = 0; g < 4; ++g) {
            int dd = g * 4;
            float w0 = ws[(dd + 0) * 260 + tid];
            float w1 = ws[(dd + 1) * 260 + tid];
            float w2 = ws[(dd + 2) * 260 + tid];
            float w3 = ws[(dd + 3) * 260 + tid];
            int dbase = c * 16 + dd;
            #pragma unroll
            for (int r = 0; r < 16; ++r) {
                float4 x = *(const float4*)&xs[r * 256 + dbase];
                float t;
                t = x.x - w0; acc[r] = fmaf(t, t, acc[r]);
                t = x.y - w1; acc[r] = fmaf(t, t, acc[r]);
                t = x.z - w2; acc[r] = fmaf(t, t, acc[r]);
                t = x.w - w3; acc[r] = fmaf(t, t, acc[r]);
            }
        }
    }
    #pragma unroll
    for (int r = 0; r < 16; ++r)
        g_protosq[(r0 + r) * M_N + tid] = acc[r];
}

// ---------------- edge graph terms + W row norms ----------------
__global__ __launch_bounds__(256) void k_edge(const float* __restrict__ E,
                                              const float* __restrict__ W) {
    __shared__ float red[256];
    const int i = blockIdx.x;
    const int j = threadIdx.x;

    float wv = W[i * M_N + j];
    float z = 0.5f * (E[i * M_N + j] + E[j * M_N + i]);
    float p = 0.0f;
    if (j != i) p = 1.0f / (1.0f + __expf(-z));
    float pd = p * g_protosq[i * M_N + j];

    float sp  = block_reduce_256(p, red);
    float spd = block_reduce_256(pd, red);
    float sw  = block_reduce_256(wv * wv, red);

    if (j == 0) {
        g_rowp[i]   = sp;
        g_rowpd[i]  = spd;
        g_factor[i] = 1.0f + TOPO_F * sp / (float)(M_N - 1);
        g_wsq[i]    = sw;
    }
}

// ---------------- GEMM: distances via 4x4 register tiling ----------------
__global__ __launch_bounds__(256) void k_gemm(const float* __restrict__ A,
                                              const float* __restrict__ W) {
    __shared__ __align__(16) float xsT[256 * 20];  // [k][row(16, pad 20)]
    __shared__ __align__(16) float ws[16 * 260];   // [kc][proto(256, pad 260)]
    __shared__ float red[256];
    __shared__ float xn[16];

    const int tid = threadIdx.x;
    const int tx = tid & 63;
    const int ty = tid >> 6;
    const int r0 = blockIdx.x * 16;

    {
        int rr = tid >> 4, c0 = tid & 15;
        const float* Ar = A + (r0 + rr) * D_N;
        float p = 0.0f;
        #pragma unroll
        for (int it = 0; it < 16; ++it) {
            float v = Ar[c0 + 16 * it];
            p = fmaf(v, v, p);
            xsT[(c0 + 16 * it) * 20 + rr] = v;
        }
        red[tid] = p;
    }
    __syncthreads();
    if (tid < 16) {
        float s = 0.0f;
        #pragma unroll
        for (int q = 0; q < 16; ++q) s += red[tid * 16 + q];
        xn[tid] = s;
    }

    float acc00=0,acc01=0,acc02=0,acc03=0;
    float acc10=0,acc11=0,acc12=0,acc13=0;
    float acc20=0,acc21=0,acc22=0,acc23=0;
    float acc30=0,acc31=0,acc32=0,acc33=0;

    for (int c = 0; c < 16; ++c) {
        __syncthreads();
        #pragma unroll
        for (int k = 0; k < 16; ++k) {
            int mm = k * 16 + (tid >> 4), dc = tid & 15;
            ws[dc * 260 + mm] = W[mm * 256 + c * 16 + dc];
        }
        __syncthreads();
        #pragma unroll
        for (int kc = 0; kc < 16; ++kc) {
            float4 x4 = *(const float4*)&xsT[(c * 16 + kc) * 20 + ty * 4];
            float4 w4 = *(const float4*)&ws[kc * 260 + tx * 4];
            acc00 = fmaf(x4.x, w4.x, acc00); acc01 = fmaf(x4.x, w4.y, acc01);
            acc02 = fmaf(x4.x, w4.z, acc02); acc03 = fmaf(x4.x, w4.w, acc03);
            acc10 = fmaf(x4.y, w4.x, acc10); acc11 = fmaf(x4.y, w4.y, acc11);
            acc12 = fmaf(x4.y, w4.z, acc12); acc13 = fmaf(x4.y, w4.w, acc13);
            acc20 = fmaf(x4.z, w4.x, acc20); acc21 = fmaf(x4.z, w4.y, acc21);
            acc22 = fmaf(x4.z, w4.z, acc22); acc23 = fmaf(x4.z, w4.w, acc23);
            acc30 = fmaf(x4.w, w4.x, acc30); acc31 = fmaf(x4.w, w4.y, acc31);
            acc32 = fmaf(x4.w, w4.z, acc32); acc33 = fmaf(x4.w, w4.w, acc33);
        }
    }

    float wn0 = g_wsq[tx * 4 + 0], wn1 = g_wsq[tx * 4 + 1];
    float wn2 = g_wsq[tx * 4 + 2], wn3 = g_wsq[tx * 4 + 3];
    #pragma unroll
    for (int r = 0; r < 4; ++r) {
        float xr = xn[ty * 4 + r];
        float a0, a1, a2, a3;
        if (r == 0) { a0=acc00; a1=acc01; a2=acc02; a3=acc03; }
        else if (r == 1) { a0=acc10; a1=acc11; a2=acc12; a3=acc13; }
        else if (r == 2) { a0=acc20; a1=acc21; a2=acc22; a3=acc23; }
        else { a0=acc30; a1=acc31; a2=acc32; a3=acc33; }
        float4 dv;
        dv.x = sqrtf(fmaxf(xr + wn0 - 2.0f * a0, 0.0f));
        dv.y = sqrtf(fmaxf(xr + wn1 - 2.0f * a1, 0.0f));
        dv.z = sqrtf(fmaxf(xr + wn2 - 2.0f * a2, 0.0f));
        dv.w = sqrtf(fmaxf(xr + wn3 - 2.0f * a3, 0.0f));
        *(float4*)&g_dist[(r0 + ty * 4 + r) * M_N + tx * 4] = dv;
    }
}

// ---------------- off-diagonal tile pair with antisymmetric reuse ------
__device__ __forceinline__ void tilepair(const unsigned* dup, unsigned di2, int lane,
                                         int J, int slot, float& sx, float& sy,
                                         float2* part) {
    const unsigned* tj = dup + J * 64;
    float sjx = 0.0f, sjy = 0.0f;
    #pragma unroll
    for (int kg = 0; kg < 8; ++kg) {
        unsigned sacc = 0u, racc = 0u;
        #pragma unroll
        for (int q = 0; q < 4; ++q) {
            const int k = kg * 4 + q;
            unsigned dj = tj[lane ^ k];
            unsigned t  = h2tanh(h2sub(di2, dj));
            unsigned r  = __shfl_xor_sync(FULLM, t, k);
            sacc = h2add(sacc, t);
            racc = h2add(racc, r);
        }
        h2acc(sacc, sx, sy);        // si += sum t
        h2accneg(racc, sjx, sjy);   // sj -= sum r
    }
    part[(J * 4 + slot) * 32 + lane] = make_float2(sjx, sjy);
}

// ---------------- rank: halved f16x2 tanh + fused final ----------------
__global__ __launch_bounds__(256) void k_rank2(float* __restrict__ out) {
    __shared__ __align__(16) unsigned dup[8 * 64];   // per-tile duplicated half2 dists
    __shared__ float2 part[8 * 4 * 32];
    __shared__ float redx[256];
    __shared__ float redy[256];
    __shared__ bool amLast;

    const int tid  = threadIdx.x;
    const int lane = tid & 31;
    const int w    = tid >> 5;
    const int p    = blockIdx.x;

    float d0  = g_dist[(2 * p + 0) * M_N + tid];
    float d1  = g_dist[(2 * p + 1) * M_N + tid];
    float fac = g_factor[tid];

    // exact fp32 row means (for fp16 centering)
    redx[tid] = d0; redy[tid] = d1;
    __syncthreads();
    #pragma unroll
    for (int s = 128; s > 0; s >>= 1) {
        if (tid < s) { redx[tid] += redx[tid + s]; redy[tid] += redy[tid + s]; }
        __syncthreads();
    }
    float m0 = redx[0] * (1.0f / 256.0f);
    float m1 = redy[0] * (1.0f / 256.0f);
    __syncthreads();

    __half2 hc = __floats2half2_rn((d0 - m0) * INV2TAU_F, (d1 - m1) * INV2TAU_F);
    unsigned hcu = *reinterpret_cast<unsigned*>(&hc);
    dup[w * 64 + lane]      = hcu;
    dup[w * 64 + 32 + lane] = hcu;
    __syncthreads();

    const unsigned di2 = dup[w * 64 + lane];
    float sx = 0.0f, sy = 0.0f;

    // ---- diagonal tile: rotation k=1..15 with reuse, k=16 unhalved ----
    {
        const unsigned* tw = dup + w * 64;
        unsigned sacc = 0u, racc = 0u;
        #pragma unroll
        for (int k = 1; k <= 15; ++k) {
            unsigned dj = tw[lane + k];
            unsigned t  = h2tanh(h2sub(di2, dj));
            unsigned r  = __shfl_sync(FULLM, t, (lane - k) & 31);
            sacc = h2add(sacc, t);
            racc = h2add(racc, r);
            if ((k & 3) == 0 || k == 15) {
                h2acc(sacc, sx, sy);
                h2accneg(racc, sx, sy);
                sacc = 0u; racc = 0u;
            }
        }
        unsigned dj = tw[lane + 16];
        unsigned t  = h2tanh(h2sub(di2, dj));
        h2acc(t, sx, sy);
    }

    // ---- off-diagonal tile pairs (each unordered pair once) ----
    tilepair(dup, di2, lane, (w + 1) & 7, 0, sx, sy, part);
    tilepair(dup, di2, lane, (w + 2) & 7, 1, sx, sy, part);
    tilepair(dup, di2, lane, (w + 3) & 7, 2, sx, sy, part);
    if (w < 4) tilepair(dup, di2, lane, w + 4, 3, sx, sy, part);
    __syncthreads();

    {
        float2 q0 = part[(w * 4 + 0) * 32 + lane];
        float2 q1 = part[(w * 4 + 1) * 32 + lane];
        float2 q2 = part[(w * 4 + 2) * 32 + lane];
        sx += q0.x + q1.x + q2.x;
        sy += q0.y + q1.y + q2.y;
        if (w >= 4) {
            float2 q3 = part[(w * 4 + 3) * 32 + lane];
            sx += q3.x; sy += q3.y;
        }
    }

    float srm0 = 127.5f + 0.5f * sx;
    float srm1 = 127.5f + 0.5f * sy;
    float contrib = exp2f(srm0 * NEIGH_LOG2) * fac * d0
                  + exp2f(srm1 * NEIGH_LOG2) * fac * d1;

    float s = block_reduce_256(contrib, redx);
    if (tid == 0) g_partial[p] = s;

    // ---- last block computes the final scalar ----
    if (tid == 0) {
        __threadfence();
        amLast = (atomicAdd(&g_ctr, 1) == NPAIR - 1);
    }
    __syncthreads();
    if (amLast) {
        float acc = 0.0f;
        #pragma unroll
        for (int i = tid; i < NPAIR; i += 256) acc += g_partial[i];
        float data_sum = block_reduce_256(acc, redx);
        float sp  = block_reduce_256(g_rowp[tid],  redx);
        float spd = block_reduce_256(g_rowpd[tid], redx);
        if (tid == 0) {
            float data_term = data_sum / ((float)B_N * (float)M_N);
            float wlen      = spd / (sp + 1e-8f);
            float sparsity  = sp / ((float)M_N * (float)M_N);
            out[0] = data_term + LEN_C_F * wlen + SP_C_F * sparsity;
        }
    }
}

// ---------------- launch ----------------
extern "C" void kernel_launch(void* const* d_in, const int* in_sizes, int n_in,
                              void* d_out, int out_size) {
    const float* data = (const float*)d_in[0];   // [4096, 256]
    const float* w    = (const float*)d_in[1];   // [256, 256]
    const float* E    = (const float*)d_in[2];   // [256, 256]
    float* out = (float*)d_out;

    sqdist_proto<<<M_N / 16, 256>>>(w);          // also resets g_ctr
    k_edge      <<<M_N, 256>>>(E, w);
    k_gemm      <<<B_N / 16, 256>>>(data, w);
    k_rank2     <<<NPAIR, 256>>>(out);
}

// round 12
// speedup vs baseline: 1.2584x; 1.2584x over previous
#include <cuda_runtime.h>
#include <cuda_fp16.h>
#include <math.h>

// Problem constants
#define B_N   4096
#define M_N   256
#define D_N   256
#define TAU_F       0.2f
#define INV2TAU_F   2.5f
#define TOPO_F      0.5f
#define LEN_C_F     0.01f
#define SP_C_F      0.001f
#define NEIGH_LOG2  (-0.18033688011112042f)   // -log2(e)/8
#define NPAIR (B_N / 2)                       // 2048 row pairs
#define FULLM 0xffffffffu

// ---------------- device scratch ----------------
__device__ float g_dist[B_N * M_N];
__device__ float g_protosq[M_N * M_N];
__device__ float g_factor[M_N];
__device__ float g_rowp[M_N];
__device__ float g_rowpd[M_N];
__device__ float g_partial[NPAIR];
__device__ int   g_ctr;

// ---------------- helpers ----------------
__device__ __forceinline__ unsigned h2tanh(unsigned x) {
    unsigned y;
    asm("tanh.approx.f16x2 %0, %1;" : "=r"(y) : "r"(x));
    return y;
}
__device__ __forceinline__ unsigned h2sub(unsigned a, unsigned b) {
    unsigned r;
    asm("sub.f16x2 %0, %1, %2;" : "=r"(r) : "r"(a), "r"(b));
    return r;
}
__device__ __forceinline__ unsigned h2add(unsigned a, unsigned b) {
    unsigned r;
    asm("add.f16x2 %0, %1, %2;" : "=r"(r) : "r"(a), "r"(b));
    return r;
}
__device__ __forceinline__ void h2acc(unsigned h2, float& a, float& b) {
    __half2 h = *reinterpret_cast<__half2*>(&h2);
    float2 f = __half22float2(h);
    a += f.x; b += f.y;
}
__device__ __forceinline__ void h2accneg(unsigned h2, float& a, float& b) {
    __half2 h = *reinterpret_cast<__half2*>(&h2);
    float2 f = __half22float2(h);
    a -= f.x; b -= f.y;
}

// packed f32x2 FMA (sm_103a): d = a*b + c on both 32-bit halves
__device__ __forceinline__ unsigned long long ffma2(unsigned long long a,
                                                    unsigned long long b,
                                                    unsigned long long c) {
    unsigned long long d;
    asm("fma.rn.f32x2 %0, %1, %2, %3;" : "=l"(d) : "l"(a), "l"(b), "l"(c));
    return d;
}
__device__ __forceinline__ unsigned long long pack2(float x) {
    unsigned long long r;
    asm("mov.b64 %0, {%1, %1};" : "=l"(r) : "f"(x));
    return r;
}
__device__ __forceinline__ float2 unpack2(unsigned long long v) {
    float2 f;
    asm("mov.b64 {%0, %1}, %2;" : "=f"(f.x), "=f"(f.y) : "l"(v));
    return f;
}

__device__ __forceinline__ float block_reduce_256(float v, float* sh) {
    int t = threadIdx.x;
    sh[t] = v;
    __syncthreads();
    #pragma unroll
    for (int s = 128; s > 0; s >>= 1) {
        if (t < s) sh[t] += sh[t + s];
        __syncthreads();
    }
    float r = sh[0];
    __syncthreads();
    return r;
}

// ---------------- fused GEMM: data dists (blocks 0..255) + proto sq dists
// (blocks 256..271). 128 threads, 16 rows x 256 protos per block.
// Thread tile: 4 rows x 8 protos (split {tx*4, 128+tx*4}), packed f32x2 FMA.
__global__ __launch_bounds__(128) void k_gemm(const float* __restrict__ A,
                                              const float* __restrict__ W) {
    __shared__ __align__(16) float xs[16 * 256];   // [row][k]  16 KB
    __shared__ __align__(16) float ws[16 * 260];   // [kc][proto pad]  16.6 KB
    __shared__ float s_wsq[256];
    __shared__ float s_xn[16];

    const int tid  = threadIdx.x;
    const int lane = tid & 31;
    const int w    = tid >> 5;          // warp 0..3
    const int tx   = tid & 31;          // proto group
    const int ty   = tid >> 5;          // row group
    const bool proto = (blockIdx.x >= 256);
    const int r0 = (proto ? (int)blockIdx.x - 256 : (int)blockIdx.x) * 16;
    const float* Ain = proto ? W : A;

    if (blockIdx.x == 0 && tid == 0) g_ctr = 0;   // reset last-block counter

    // ---- W row norms (warp-cooperative, L2-hot, redundant per block) ----
    #pragma unroll 4
    for (int r = w * 64; r < w * 64 + 64; ++r) {
        const float4* Wr = (const float4*)(W + r * D_N);
        float4 a = Wr[lane], b = Wr[lane + 32];
        float p = a.x*a.x + a.y*a.y + a.z*a.z + a.w*a.w
                + b.x*b.x + b.y*b.y + b.z*b.z + b.w*b.w;
        #pragma unroll
        for (int off = 16; off > 0; off >>= 1) p += __shfl_xor_sync(FULLM, p, off);
        if (lane == 0) s_wsq[r] = p;
    }

    // ---- load A tile [16][256] row-major ----
    #pragma unroll
    for (int it = 0; it < 8; ++it) {
        int fidx = it * 128 + tid;           // float4 index 0..1023
        int row = fidx >> 6, k4 = fidx & 63;
        float4 v = ((const float4*)(Ain + (r0 + row) * D_N))[k4];
        *(float4*)&xs[row * 256 + k4 * 4] = v;
    }
    __syncthreads();

    // ---- row norms of the tile ----
    {
        int r = w * 4 + (lane >> 5); // warp handles rows w*4..w*4+3 sequentially
        #pragma unroll
        for (int rr = 0; rr < 4; ++rr) {
            int row = w * 4 + rr;
            const float4* xr4 = (const float4*)&xs[row * 256];
            float4 a = xr4[lane], b = xr4[lane + 32];
            float p = a.x*a.x + a.y*a.y + a.z*a.z + a.w*a.w
                    + b.x*b.x + b.y*b.y + b.z*b.z + b.w*b.w;
            #pragma unroll
            for (int off = 16; off > 0; off >>= 1) p += __shfl_xor_sync(FULLM, p, off);
            if (lane == 0) s_xn[row] = p;
        }
        (void)r;
    }

    unsigned long long acc[4][4];
    #pragma unroll
    for (int r = 0; r < 4; ++r)
        #pragma unroll
        for (int q = 0; q < 4; ++q) acc[r][q] = 0ull;

    for (int c = 0; c < 16; ++c) {
        __syncthreads();
        // stage W[:, c*16 : c*16+16] transposed: ws[dc][proto]
        #pragma unroll
        for (int it = 0; it < 32; ++it) {
            int idx = it * 128 + tid;
            int mm = idx >> 4, dc = idx & 15;
            ws[dc * 260 + mm] = W[mm * 256 + c * 16 + dc];
        }
        __syncthreads();

        #pragma unroll
        for (int kq = 0; kq < 4; ++kq) {
            float4 xr[4];
            #pragma unroll
            for (int r = 0; r < 4; ++r)
                xr[r] = *(const float4*)&xs[(ty * 4 + r) * 256 + c * 16 + kq * 4];
            #pragma unroll
            for (int k2 = 0; k2 < 4; ++k2) {
                const int kc = kq * 4 + k2;
                ulonglong2 wA = *(const ulonglong2*)&ws[kc * 260 + tx * 4];
                ulonglong2 wB = *(const ulonglong2*)&ws[kc * 260 + 128 + tx * 4];
                #pragma unroll
                for (int r = 0; r < 4; ++r) {
                    float xv = (k2 == 0) ? xr[r].x : (k2 == 1) ? xr[r].y
                             : (k2 == 2) ? xr[r].z : xr[r].w;
                    unsigned long long xx = pack2(xv);
                    acc[r][0] = ffma2(xx, wA.x, acc[r][0]);
                    acc[r][1] = ffma2(xx, wA.y, acc[r][1]);
                    acc[r][2] = ffma2(xx, wB.x, acc[r][2]);
                    acc[r][3] = ffma2(xx, wB.y, acc[r][3]);
                }
            }
        }
    }

    // ---- epilogue ----
    #pragma unroll
    for (int r = 0; r < 4; ++r) {
        int row = r0 + ty * 4 + r;
        float xr = s_xn[ty * 4 + r];
        float2 a0 = unpack2(acc[r][0]), a1 = unpack2(acc[r][1]);
        float2 a2 = unpack2(acc[r][2]), a3 = unpack2(acc[r][3]);
        float4 dA, dB;
        dA.x = fmaxf(xr + s_wsq[tx * 4 + 0]       - 2.0f * a0.x, 0.0f);
        dA.y = fmaxf(xr + s_wsq[tx * 4 + 1]       - 2.0f * a0.y, 0.0f);
        dA.z = fmaxf(xr + s_wsq[tx * 4 + 2]       - 2.0f * a1.x, 0.0f);
        dA.w = fmaxf(xr + s_wsq[tx * 4 + 3]       - 2.0f * a1.y, 0.0f);
        dB.x = fmaxf(xr + s_wsq[128 + tx * 4 + 0] - 2.0f * a2.x, 0.0f);
        dB.y = fmaxf(xr + s_wsq[128 + tx * 4 + 1] - 2.0f * a2.y, 0.0f);
        dB.z = fmaxf(xr + s_wsq[128 + tx * 4 + 2] - 2.0f * a3.x, 0.0f);
        dB.w = fmaxf(xr + s_wsq[128 + tx * 4 + 3] - 2.0f * a3.y, 0.0f);
        if (!proto) {
            dA.x = sqrtf(dA.x); dA.y = sqrtf(dA.y); dA.z = sqrtf(dA.z); dA.w = sqrtf(dA.w);
            dB.x = sqrtf(dB.x); dB.y = sqrtf(dB.y); dB.z = sqrtf(dB.z); dB.w = sqrtf(dB.w);
            *(float4*)&g_dist[row * M_N + tx * 4]       = dA;
            *(float4*)&g_dist[row * M_N + 128 + tx * 4] = dB;
        } else {
            *(float4*)&g_protosq[row * M_N + tx * 4]       = dA;
            *(float4*)&g_protosq[row * M_N + 128 + tx * 4] = dB;
        }
    }
}

// ---------------- edge graph terms ----------------
__global__ __launch_bounds__(256) void k_edge(const float* __restrict__ E) {
    __shared__ float red[256];
    const int i = blockIdx.x;
    const int j = threadIdx.x;

    float z = 0.5f * (E[i * M_N + j] + E[j * M_N + i]);
    float p = 0.0f;
    if (j != i) p = 1.0f / (1.0f + __expf(-z));
    float pd = p * g_protosq[i * M_N + j];

    float sp  = block_reduce_256(p, red);
    float spd = block_reduce_256(pd, red);

    if (j == 0) {
        g_rowp[i]   = sp;
        g_rowpd[i]  = spd;
        g_factor[i] = 1.0f + TOPO_F * sp / (float)(M_N - 1);
    }
}

// ---------------- off-diagonal tile pair with antisymmetric reuse ------
__device__ __forceinline__ void tilepair(const unsigned* dup, unsigned di2, int lane,
                                         int J, int slot, float& sx, float& sy,
                                         float2* part) {
    const unsigned* tj = dup + J * 64;
    float sjx = 0.0f, sjy = 0.0f;
    #pragma unroll
    for (int kg = 0; kg < 8; ++kg) {
        unsigned sacc = 0u, racc = 0u;
        #pragma unroll
        for (int q = 0; q < 4; ++q) {
            const int k = kg * 4 + q;
            unsigned dj = tj[lane ^ k];
            unsigned t  = h2tanh(h2sub(di2, dj));
            unsigned r  = __shfl_xor_sync(FULLM, t, k);
            sacc = h2add(sacc, t);
            racc = h2add(racc, r);
        }
        h2acc(sacc, sx, sy);        // si += sum t
        h2accneg(racc, sjx, sjy);   // sj -= sum r
    }
    part[(J * 4 + slot) * 32 + lane] = make_float2(sjx, sjy);
}

// ---------------- rank: halved f16x2 tanh + fused final ----------------
__global__ __launch_bounds__(256) void k_rank2(float* __restrict__ out) {
    __shared__ __align__(16) unsigned dup[8 * 64];   // per-tile duplicated half2 dists
    __shared__ float2 part[8 * 4 * 32];
    __shared__ float redx[256];
    __shared__ float redy[256];
    __shared__ bool amLast;

    const int tid  = threadIdx.x;
    const int lane = tid & 31;
    const int w    = tid >> 5;
    const int p    = blockIdx.x;

    float d0  = g_dist[(2 * p + 0) * M_N + tid];
    float d1  = g_dist[(2 * p + 1) * M_N + tid];
    float fac = g_factor[tid];

    // exact fp32 row means (for fp16 centering)
    redx[tid] = d0; redy[tid] = d1;
    __syncthreads();
    #pragma unroll
    for (int s = 128; s > 0; s >>= 1) {
        if (tid < s) { redx[tid] += redx[tid + s]; redy[tid] += redy[tid + s]; }
        __syncthreads();
    }
    float m0 = redx[0] * (1.0f / 256.0f);
    float m1 = redy[0] * (1.0f / 256.0f);
    __syncthreads();

    __half2 hc = __floats2half2_rn((d0 - m0) * INV2TAU_F, (d1 - m1) * INV2TAU_F);
    unsigned hcu = *reinterpret_cast<unsigned*>(&hc);
    dup[w * 64 + lane]      = hcu;
    dup[w * 64 + 32 + lane] = hcu;
    __syncthreads();

    const unsigned di2 = dup[w * 64 + lane];
    float sx = 0.0f, sy = 0.0f;

    // ---- diagonal tile: rotation k=1..15 with reuse, k=16 unhalved ----
    {
        const unsigned* tw = dup + w * 64;
        unsigned sacc = 0u, racc = 0u;
        #pragma unroll
        for (int k = 1; k <= 15; ++k) {
            unsigned dj = tw[lane + k];
            unsigned t  = h2tanh(h2sub(di2, dj));
            unsigned r  = __shfl_sync(FULLM, t, (lane - k) & 31);
            sacc = h2add(sacc, t);
            racc = h2add(racc, r);
            if ((k & 3) == 0 || k == 15) {
                h2acc(sacc, sx, sy);
                h2accneg(racc, sx, sy);
                sacc = 0u; racc = 0u;
            }
        }
        unsigned dj = tw[lane + 16];
        unsigned t  = h2tanh(h2sub(di2, dj));
        h2acc(t, sx, sy);
    }

    // ---- off-diagonal tile pairs (each unordered pair once) ----
    tilepair(dup, di2, lane, (w + 1) & 7, 0, sx, sy, part);
    tilepair(dup, di2, lane, (w + 2) & 7, 1, sx, sy, part);
    tilepair(dup, di2, lane, (w + 3) & 7, 2, sx, sy, part);
    if (w < 4) tilepair(dup, di2, lane, w + 4, 3, sx, sy, part);
    __syncthreads();

    {
        float2 q0 = part[(w * 4 + 0) * 32 + lane];
        float2 q1 = part[(w * 4 + 1) * 32 + lane];
        float2 q2 = part[(w * 4 + 2) * 32 + lane];
        sx += q0.x + q1.x + q2.x;
        sy += q0.y + q1.y + q2.y;
        if (w >= 4) {
            float2 q3 = part[(w * 4 + 3) * 32 + lane];
            sx += q3.x; sy += q3.y;
        }
    }

    float srm0 = 127.5f + 0.5f * sx;
    float srm1 = 127.5f + 0.5f * sy;
    float contrib = exp2f(srm0 * NEIGH_LOG2) * fac * d0
                  + exp2f(srm1 * NEIGH_LOG2) * fac * d1;

    float s = block_reduce_256(contrib, redx);
    if (tid == 0) g_partial[p] = s;

    // ---- last block computes the final scalar ----
    if (tid == 0) {
        __threadfence();
        amLast = (atomicAdd(&g_ctr, 1) == NPAIR - 1);
    }
    __syncthreads();
    if (amLast) {
        float acc = 0.0f;
        #pragma unroll
        for (int i = tid; i < NPAIR; i += 256) acc += g_partial[i];
        float data_sum = block_reduce_256(acc, redx);
        float sp  = block_reduce_256(g_rowp[tid],  redx);
        float spd = block_reduce_256(g_rowpd[tid], redx);
        if (tid == 0) {
            float data_term = data_sum / ((float)B_N * (float)M_N);
            float wlen      = spd / (sp + 1e-8f);
            float sparsity  = sp / ((float)M_N * (float)M_N);
            out[0] = data_term + LEN_C_F * wlen + SP_C_F * sparsity;
        }
    }
}

// ---------------- launch ----------------
extern "C" void kernel_launch(void* const* d_in, const int* in_sizes, int n_in,
                              void* d_out, int out_size) {
    const float* data = (const float*)d_in[0];   // [4096, 256]
    const float* w    = (const float*)d_in[1];   // [256, 256]
    const float* E    = (const float*)d_in[2];   // [256, 256]
    float* out = (float*)d_out;

    k_gemm  <<<272, 128>>>(data, w);   // data dists + proto sq dists + ctr reset
    k_edge  <<<M_N, 256>>>(E);
    k_rank2 <<<NPAIR, 256>>>(out);
}

// round 13
// speedup vs baseline: 1.3762x; 1.0936x over previous
#include <cuda_runtime.h>
#include <cuda_fp16.h>
#include <math.h>

// Problem constants
#define B_N   4096
#define M_N   256
#define D_N   256
#define TAU_F       0.2f
#define INV2TAU_F   2.5f
#define TOPO_F      0.5f
#define LEN_C_F     0.01f
#define SP_C_F      0.001f
#define NEIGH_LOG2  (-0.18033688011112042f)   // -log2(e)/8
#define NPAIR (B_N / 2)                       // 2048 row pairs
#define FULLM 0xffffffffu

// ---------------- device scratch ----------------
__device__ float g_dist[B_N * M_N];
__device__ float g_protosq[M_N * M_N];
__device__ float g_factor[M_N];
__device__ float g_rowp[M_N];
__device__ float g_rowpd[M_N];
__device__ float g_partial[NPAIR];
__device__ int   g_ctr;

// ---------------- helpers ----------------
__device__ __forceinline__ unsigned h2tanh(unsigned x) {
    unsigned y;
    asm("tanh.approx.f16x2 %0, %1;" : "=r"(y) : "r"(x));
    return y;
}
__device__ __forceinline__ unsigned h2sub(unsigned a, unsigned b) {
    unsigned r;
    asm("sub.f16x2 %0, %1, %2;" : "=r"(r) : "r"(a), "r"(b));
    return r;
}
__device__ __forceinline__ unsigned h2add(unsigned a, unsigned b) {
    unsigned r;
    asm("add.f16x2 %0, %1, %2;" : "=r"(r) : "r"(a), "r"(b));
    return r;
}
__device__ __forceinline__ void h2acc(unsigned h2, float& a, float& b) {
    __half2 h = *reinterpret_cast<__half2*>(&h2);
    float2 f = __half22float2(h);
    a += f.x; b += f.y;
}
__device__ __forceinline__ void h2accneg(unsigned h2, float& a, float& b) {
    __half2 h = *reinterpret_cast<__half2*>(&h2);
    float2 f = __half22float2(h);
    a -= f.x; b -= f.y;
}

// packed f32x2 FMA (sm_103a)
__device__ __forceinline__ unsigned long long ffma2(unsigned long long a,
                                                    unsigned long long b,
                                                    unsigned long long c) {
    unsigned long long d;
    asm("fma.rn.f32x2 %0, %1, %2, %3;" : "=l"(d) : "l"(a), "l"(b), "l"(c));
    return d;
}
__device__ __forceinline__ unsigned long long pack2(float x) {
    unsigned long long r;
    asm("mov.b64 %0, {%1, %1};" : "=l"(r) : "f"(x));
    return r;
}
__device__ __forceinline__ float2 unpack2(unsigned long long v) {
    float2 f;
    asm("mov.b64 {%0, %1}, %2;" : "=f"(f.x), "=f"(f.y) : "l"(v));
    return f;
}

__device__ __forceinline__ float block_reduce_256(float v, float* sh) {
    int t = threadIdx.x;
    sh[t] = v;
    __syncthreads();
    #pragma unroll
    for (int s = 128; s > 0; s >>= 1) {
        if (t < s) sh[t] += sh[t + s];
        __syncthreads();
    }
    float r = sh[0];
    __syncthreads();
    return r;
}

// ---------------- fused GEMM: data dists (blocks 0..127) + proto sq dists
// (blocks 128..135). 256 threads, 32 rows x 256 protos per block.
// Thread tile: 4 rows x 8 protos; packed f32x2 FMA; double-buffered W staging.
__global__ __launch_bounds__(256) void k_gemm(const float* __restrict__ A,
                                              const float* __restrict__ W) {
    __shared__ __align__(16) float xs[32 * 256];        // 32 KB  [row][k]
    __shared__ __align__(16) float ws[2][16 * 260];     // 33.3 KB [buf][kc][proto pad]
    __shared__ float s_wsq[256];
    __shared__ float s_xn[32];

    const int tid  = threadIdx.x;
    const int lane = tid & 31;
    const int w8   = tid >> 5;          // warp 0..7
    const int tx   = tid & 31;          // proto group: {tx*4, 128+tx*4}
    const int ty   = tid >> 5;          // row group: ty*4 .. ty*4+3
    const bool proto = (blockIdx.x >= 128);
    const int r0 = (proto ? (int)blockIdx.x - 128 : (int)blockIdx.x) * 32;
    const float* Ain = proto ? W : A;

    if (blockIdx.x == 0 && tid == 0) g_ctr = 0;   // reset last-block counter

    // ---- W row norms: warp w8 handles rows w8*32 .. +31 (L2-hot LDG) ----
    #pragma unroll 4
    for (int r = w8 * 32; r < w8 * 32 + 32; ++r) {
        const float4* Wr = (const float4*)(W + r * D_N);
        float4 a = Wr[lane], b = Wr[lane + 32];
        float p = a.x*a.x + a.y*a.y + a.z*a.z + a.w*a.w
                + b.x*b.x + b.y*b.y + b.z*b.z + b.w*b.w;
        #pragma unroll
        for (int off = 16; off > 0; off >>= 1) p += __shfl_xor_sync(FULLM, p, off);
        if (lane == 0) s_wsq[r] = p;
    }

    // ---- load A tile [32][256] (coalesced float4) ----
    #pragma unroll
    for (int it = 0; it < 8; ++it) {
        int fidx = it * 256 + tid;           // float4 index 0..2047
        int row = fidx >> 6, k4 = fidx & 63;
        float4 v = ((const float4*)(Ain + (r0 + row) * D_N))[k4];
        *(float4*)&xs[row * 256 + k4 * 4] = v;
    }
    __syncthreads();

    // ---- row norms of the A tile: warp w8 -> rows w8*4 .. +3 ----
    #pragma unroll
    for (int rr = 0; rr < 4; ++rr) {
        int row = w8 * 4 + rr;
        const float4* xr4 = (const float4*)&xs[row * 256];
        float4 a = xr4[lane], b = xr4[lane + 32];
        float p = a.x*a.x + a.y*a.y + a.z*a.z + a.w*a.w
                + b.x*b.x + b.y*b.y + b.z*b.z + b.w*b.w;
        #pragma unroll
        for (int off = 16; off > 0; off >>= 1) p += __shfl_xor_sync(FULLM, p, off);
        if (lane == 0) s_xn[row] = p;
    }

    // ---- stage chunk 0 ----
    {
        #pragma unroll
        for (int it = 0; it < 4; ++it) {
            int fidx = it * 256 + tid;           // 0..1023
            int mm = fidx >> 2, dc4 = fidx & 3;
            float4 v = *(const float4*)&W[mm * 256 + /*c=0*/ dc4 * 4];
            ws[0][(dc4 * 4 + 0) * 260 + mm] = v.x;
            ws[0][(dc4 * 4 + 1) * 260 + mm] = v.y;
            ws[0][(dc4 * 4 + 2) * 260 + mm] = v.z;
            ws[0][(dc4 * 4 + 3) * 260 + mm] = v.w;
        }
    }
    __syncthreads();

    unsigned long long acc[4][4];
    #pragma unroll
    for (int r = 0; r < 4; ++r)
        #pragma unroll
        for (int q = 0; q < 4; ++q) acc[r][q] = 0ull;

    #pragma unroll 1
    for (int c = 0; c < 16; ++c) {
        const int b = c & 1;
        // prefetch next chunk into registers (LDG latency hidden by compute)
        float4 pre[4];
        if (c < 15) {
            #pragma unroll
            for (int it = 0; it < 4; ++it) {
                int fidx = it * 256 + tid;
                int mm = fidx >> 2, dc4 = fidx & 3;
                pre[it] = *(const float4*)&W[mm * 256 + (c + 1) * 16 + dc4 * 4];
            }
        }

        // compute chunk c from ws[b]
        const float* wsb = ws[b];
        #pragma unroll
        for (int kq = 0; kq < 4; ++kq) {
            float4 xr[4];
            #pragma unroll
            for (int r = 0; r < 4; ++r)
                xr[r] = *(const float4*)&xs[(ty * 4 + r) * 256 + c * 16 + kq * 4];
            #pragma unroll
            for (int k2 = 0; k2 < 4; ++k2) {
                const int kc = kq * 4 + k2;
                ulonglong2 wA = *(const ulonglong2*)&wsb[kc * 260 + tx * 4];
                ulonglong2 wB = *(const ulonglong2*)&wsb[kc * 260 + 128 + tx * 4];
                #pragma unroll
                for (int r = 0; r < 4; ++r) {
                    float xv = (k2 == 0) ? xr[r].x : (k2 == 1) ? xr[r].y
                             : (k2 == 2) ? xr[r].z : xr[r].w;
                    unsigned long long xx = pack2(xv);
                    acc[r][0] = ffma2(xx, wA.x, acc[r][0]);
                    acc[r][1] = ffma2(xx, wA.y, acc[r][1]);
                    acc[r][2] = ffma2(xx, wB.x, acc[r][2]);
                    acc[r][3] = ffma2(xx, wB.y, acc[r][3]);
                }
            }
        }

        // stage next chunk into the other buffer
        if (c < 15) {
            float* wsn = ws[1 - b];
            #pragma unroll
            for (int it = 0; it < 4; ++it) {
                int fidx = it * 256 + tid;
                int mm = fidx >> 2, dc4 = fidx & 3;
                wsn[(dc4 * 4 + 0) * 260 + mm] = pre[it].x;
                wsn[(dc4 * 4 + 1) * 260 + mm] = pre[it].y;
                wsn[(dc4 * 4 + 2) * 260 + mm] = pre[it].z;
                wsn[(dc4 * 4 + 3) * 260 + mm] = pre[it].w;
            }
            __syncthreads();
        }
    }

    // ---- epilogue ----
    #pragma unroll
    for (int r = 0; r < 4; ++r) {
        int row = r0 + ty * 4 + r;
        float xr = s_xn[ty * 4 + r];
        float2 a0 = unpack2(acc[r][0]), a1 = unpack2(acc[r][1]);
        float2 a2 = unpack2(acc[r][2]), a3 = unpack2(acc[r][3]);
        float4 dA, dB;
        dA.x = fmaxf(xr + s_wsq[tx * 4 + 0]       - 2.0f * a0.x, 0.0f);
        dA.y = fmaxf(xr + s_wsq[tx * 4 + 1]       - 2.0f * a0.y, 0.0f);
        dA.z = fmaxf(xr + s_wsq[tx * 4 + 2]       - 2.0f * a1.x, 0.0f);
        dA.w = fmaxf(xr + s_wsq[tx * 4 + 3]       - 2.0f * a1.y, 0.0f);
        dB.x = fmaxf(xr + s_wsq[128 + tx * 4 + 0] - 2.0f * a2.x, 0.0f);
        dB.y = fmaxf(xr + s_wsq[128 + tx * 4 + 1] - 2.0f * a2.y, 0.0f);
        dB.z = fmaxf(xr + s_wsq[128 + tx * 4 + 2] - 2.0f * a3.x, 0.0f);
        dB.w = fmaxf(xr + s_wsq[128 + tx * 4 + 3] - 2.0f * a3.y, 0.0f);
        if (!proto) {
            dA.x = sqrtf(dA.x); dA.y = sqrtf(dA.y); dA.z = sqrtf(dA.z); dA.w = sqrtf(dA.w);
            dB.x = sqrtf(dB.x); dB.y = sqrtf(dB.y); dB.z = sqrtf(dB.z); dB.w = sqrtf(dB.w);
            *(float4*)&g_dist[row * M_N + tx * 4]       = dA;
            *(float4*)&g_dist[row * M_N + 128 + tx * 4] = dB;
        } else {
            *(float4*)&g_protosq[row * M_N + tx * 4]       = dA;
            *(float4*)&g_protosq[row * M_N + 128 + tx * 4] = dB;
        }
    }
}

// ---------------- edge graph terms ----------------
__global__ __launch_bounds__(256) void k_edge(const float* __restrict__ E) {
    __shared__ float red[256];
    const int i = blockIdx.x;
    const int j = threadIdx.x;

    float z = 0.5f * (E[i * M_N + j] + E[j * M_N + i]);
    float p = 0.0f;
    if (j != i) p = 1.0f / (1.0f + __expf(-z));
    float pd = p * g_protosq[i * M_N + j];

    float sp  = block_reduce_256(p, red);
    float spd = block_reduce_256(pd, red);

    if (j == 0) {
        g_rowp[i]   = sp;
        g_rowpd[i]  = spd;
        g_factor[i] = 1.0f + TOPO_F * sp / (float)(M_N - 1);
    }
}

// ---------------- off-diagonal tile pair with antisymmetric reuse ------
__device__ __forceinline__ void tilepair(const unsigned* dup, unsigned di2, int lane,
                                         int J, int slot, float& sx, float& sy,
                                         float2* part) {
    const unsigned* tj = dup + J * 64;
    float sjx = 0.0f, sjy = 0.0f;
    #pragma unroll
    for (int kg = 0; kg < 8; ++kg) {
        unsigned sacc = 0u, racc = 0u;
        #pragma unroll
        for (int q = 0; q < 4; ++q) {
            const int k = kg * 4 + q;
            unsigned dj = tj[lane ^ k];
            unsigned t  = h2tanh(h2sub(di2, dj));
            unsigned r  = __shfl_xor_sync(FULLM, t, k);
            sacc = h2add(sacc, t);
            racc = h2add(racc, r);
        }
        h2acc(sacc, sx, sy);        // si += sum t
        h2accneg(racc, sjx, sjy);   // sj -= sum r
    }
    part[(J * 4 + slot) * 32 + lane] = make_float2(sjx, sjy);
}

// ---------------- rank: halved f16x2 tanh + fused final ----------------
__global__ __launch_bounds__(256) void k_rank2(float* __restrict__ out) {
    __shared__ __align__(16) unsigned dup[8 * 64];   // per-tile duplicated half2 dists
    __shared__ float2 part[8 * 4 * 32];
    __shared__ float redx[256];
    __shared__ float redy[256];
    __shared__ bool amLast;

    const int tid  = threadIdx.x;
    const int lane = tid & 31;
    const int w    = tid >> 5;
    const int p    = blockIdx.x;

    float d0  = g_dist[(2 * p + 0) * M_N + tid];
    float d1  = g_dist[(2 * p + 1) * M_N + tid];
    float fac = g_factor[tid];

    // exact fp32 row means (for fp16 centering)
    redx[tid] = d0; redy[tid] = d1;
    __syncthreads();
    #pragma unroll
    for (int s = 128; s > 0; s >>= 1) {
        if (tid < s) { redx[tid] += redx[tid + s]; redy[tid] += redy[tid + s]; }
        __syncthreads();
    }
    float m0 = redx[0] * (1.0f / 256.0f);
    float m1 = redy[0] * (1.0f / 256.0f);
    __syncthreads();

    __half2 hc = __floats2half2_rn((d0 - m0) * INV2TAU_F, (d1 - m1) * INV2TAU_F);
    unsigned hcu = *reinterpret_cast<unsigned*>(&hc);
    dup[w * 64 + lane]      = hcu;
    dup[w * 64 + 32 + lane] = hcu;
    __syncthreads();

    const unsigned di2 = dup[w * 64 + lane];
    float sx = 0.0f, sy = 0.0f;

    // ---- diagonal tile: rotation k=1..15 with reuse, k=16 unhalved ----
    {
        const unsigned* tw = dup + w * 64;
        unsigned sacc = 0u, racc = 0u;
        #pragma unroll
        for (int k = 1; k <= 15; ++k) {
            unsigned dj = tw[lane + k];
            unsigned t  = h2tanh(h2sub(di2, dj));
            unsigned r  = __shfl_sync(FULLM, t, (lane - k) & 31);
            sacc = h2add(sacc, t);
            racc = h2add(racc, r);
            if ((k & 3) == 0 || k == 15) {
                h2acc(sacc, sx, sy);
                h2accneg(racc, sx, sy);
                sacc = 0u; racc = 0u;
            }
        }
        unsigned dj = tw[lane + 16];
        unsigned t  = h2tanh(h2sub(di2, dj));
        h2acc(t, sx, sy);
    }

    // ---- off-diagonal tile pairs (each unordered pair once) ----
    tilepair(dup, di2, lane, (w + 1) & 7, 0, sx, sy, part);
    tilepair(dup, di2, lane, (w + 2) & 7, 1, sx, sy, part);
    tilepair(dup, di2, lane, (w + 3) & 7, 2, sx, sy, part);
    if (w < 4) tilepair(dup, di2, lane, w + 4, 3, sx, sy, part);
    __syncthreads();

    {
        float2 q0 = part[(w * 4 + 0) * 32 + lane];
        float2 q1 = part[(w * 4 + 1) * 32 + lane];
        float2 q2 = part[(w * 4 + 2) * 32 + lane];
        sx += q0.x + q1.x + q2.x;
        sy += q0.y + q1.y + q2.y;
        if (w >= 4) {
            float2 q3 = part[(w * 4 + 3) * 32 + lane];
            sx += q3.x; sy += q3.y;
        }
    }

    float srm0 = 127.5f + 0.5f * sx;
    float srm1 = 127.5f + 0.5f * sy;
    float contrib = exp2f(srm0 * NEIGH_LOG2) * fac * d0
                  + exp2f(srm1 * NEIGH_LOG2) * fac * d1;

    float s = block_reduce_256(contrib, redx);
    if (tid == 0) g_partial[p] = s;

    // ---- last block computes the final scalar ----
    if (tid == 0) {
        __threadfence();
        amLast = (atomicAdd(&g_ctr, 1) == NPAIR - 1);
    }
    __syncthreads();
    if (amLast) {
        float acc = 0.0f;
        #pragma unroll
        for (int i = tid; i < NPAIR; i += 256) acc += g_partial[i];
        float data_sum = block_reduce_256(acc, redx);
        float sp  = block_reduce_256(g_rowp[tid],  redx);
        float spd = block_reduce_256(g_rowpd[tid], redx);
        if (tid == 0) {
            float data_term = data_sum / ((float)B_N * (float)M_N);
            float wlen      = spd / (sp + 1e-8f);
            float sparsity  = sp / ((float)M_N * (float)M_N);
            out[0] = data_term + LEN_C_F * wlen + SP_C_F * sparsity;
        }
    }
}

// ---------------- launch ----------------
extern "C" void kernel_launch(void* const* d_in, const int* in_sizes, int n_in,
                              void* d_out, int out_size) {
    const float* data = (const float*)d_in[0];   // [4096, 256]
    const float* w    = (const float*)d_in[1];   // [256, 256]
    const float* E    = (const float*)d_in[2];   // [256, 256]
    float* out = (float*)d_out;

    k_gemm  <<<136, 256>>>(data, w);   // data dists + proto sq dists + ctr reset
    k_edge  <<<M_N, 256>>>(E);
    k_rank2 <<<NPAIR, 256>>>(out);
}

// round 14
// speedup vs baseline: 1.3856x; 1.0068x over previous
#include <cuda_runtime.h>
#include <cuda_fp16.h>
#include <math.h>

// Problem constants
#define B_N   4096
#define M_N   256
#define D_N   256
#define TAU_F       0.2f
#define INV2TAU_F   2.5f
#define TOPO_F      0.5f
#define LEN_C_F     0.01f
#define SP_C_F      0.001f
#define NEIGH_LOG2  (-0.18033688011112042f)   // -log2(e)/8
#define NPAIR (B_N / 2)                       // 2048 row pairs
#define FULLM 0xffffffffu

// ---------------- device scratch ----------------
__device__ float g_dist[B_N * M_N];
__device__ float g_protosq[M_N * M_N];
__device__ float g_factor[M_N];
__device__ float g_rowp[M_N];
__device__ float g_rowpd[M_N];
__device__ float g_partial[NPAIR];
__device__ int   g_ctr;

// ---------------- helpers ----------------
__device__ __forceinline__ unsigned h2tanh(unsigned x) {
    unsigned y;
    asm("tanh.approx.f16x2 %0, %1;" : "=r"(y) : "r"(x));
    return y;
}
__device__ __forceinline__ unsigned h2sub(unsigned a, unsigned b) {
    unsigned r;
    asm("sub.f16x2 %0, %1, %2;" : "=r"(r) : "r"(a), "r"(b));
    return r;
}
__device__ __forceinline__ unsigned h2add(unsigned a, unsigned b) {
    unsigned r;
    asm("add.f16x2 %0, %1, %2;" : "=r"(r) : "r"(a), "r"(b));
    return r;
}
__device__ __forceinline__ void h2acc(unsigned h2, float& a, float& b) {
    __half2 h = *reinterpret_cast<__half2*>(&h2);
    float2 f = __half22float2(h);
    a += f.x; b += f.y;
}
__device__ __forceinline__ void h2accneg(unsigned h2, float& a, float& b) {
    __half2 h = *reinterpret_cast<__half2*>(&h2);
    float2 f = __half22float2(h);
    a -= f.x; b -= f.y;
}

// packed f32x2 FMA (sm_103a)
__device__ __forceinline__ unsigned long long ffma2(unsigned long long a,
                                                    unsigned long long b,
                                                    unsigned long long c) {
    unsigned long long d;
    asm("fma.rn.f32x2 %0, %1, %2, %3;" : "=l"(d) : "l"(a), "l"(b), "l"(c));
    return d;
}
__device__ __forceinline__ unsigned long long pack2(float x) {
    unsigned long long r;
    asm("mov.b64 %0, {%1, %1};" : "=l"(r) : "f"(x));
    return r;
}
__device__ __forceinline__ float2 unpack2(unsigned long long v) {
    float2 f;
    asm("mov.b64 {%0, %1}, %2;" : "=f"(f.x), "=f"(f.y) : "l"(v));
    return f;
}

__device__ __forceinline__ float block_reduce_256(float v, float* sh) {
    int t = threadIdx.x;
    sh[t] = v;
    __syncthreads();
    #pragma unroll
    for (int s = 128; s > 0; s >>= 1) {
        if (t < s) sh[t] += sh[t + s];
        __syncthreads();
    }
    float r = sh[0];
    __syncthreads();
    return r;
}

// ---------------- fused GEMM: data dists (blocks 0..127) + proto sq dists
// (blocks 128..135). 256 threads, 32 rows x 256 protos per block.
// Thread tile: 4 rows x 8 protos; packed f32x2 FMA; double-buffered W staging.
__global__ __launch_bounds__(256) void k_gemm(const float* __restrict__ A,
                                              const float* __restrict__ W) {
    __shared__ __align__(16) float xs[32 * 256];        // 32 KB  [row][k]
    __shared__ __align__(16) float ws[2][16 * 260];     // 33.3 KB [buf][kc][proto pad]
    __shared__ float s_wsq[256];
    __shared__ float s_xn[32];

    const int tid  = threadIdx.x;
    const int lane = tid & 31;
    const int w8   = tid >> 5;          // warp 0..7
    const int tx   = tid & 31;          // proto group: {tx*4, 128+tx*4}
    const int ty   = tid >> 5;          // row group: ty*4 .. ty*4+3
    const bool proto = (blockIdx.x >= 128);
    const int r0 = (proto ? (int)blockIdx.x - 128 : (int)blockIdx.x) * 32;
    const float* Ain = proto ? W : A;

    if (blockIdx.x == 0 && tid == 0) g_ctr = 0;   // reset last-block counter

    // ---- W row norms: warp w8 handles rows w8*32 .. +31 (L2-hot LDG) ----
    #pragma unroll 4
    for (int r = w8 * 32; r < w8 * 32 + 32; ++r) {
        const float4* Wr = (const float4*)(W + r * D_N);
        float4 a = Wr[lane], b = Wr[lane + 32];
        float p = a.x*a.x + a.y*a.y + a.z*a.z + a.w*a.w
                + b.x*b.x + b.y*b.y + b.z*b.z + b.w*b.w;
        #pragma unroll
        for (int off = 16; off > 0; off >>= 1) p += __shfl_xor_sync(FULLM, p, off);
        if (lane == 0) s_wsq[r] = p;
    }

    // ---- load A tile [32][256] (coalesced float4) ----
    #pragma unroll
    for (int it = 0; it < 8; ++it) {
        int fidx = it * 256 + tid;           // float4 index 0..2047
        int row = fidx >> 6, k4 = fidx & 63;
        float4 v = ((const float4*)(Ain + (r0 + row) * D_N))[k4];
        *(float4*)&xs[row * 256 + k4 * 4] = v;
    }
    __syncthreads();

    // ---- row norms of the A tile: warp w8 -> rows w8*4 .. +3 ----
    #pragma unroll
    for (int rr = 0; rr < 4; ++rr) {
        int row = w8 * 4 + rr;
        const float4* xr4 = (const float4*)&xs[row * 256];
        float4 a = xr4[lane], b = xr4[lane + 32];
        float p = a.x*a.x + a.y*a.y + a.z*a.z + a.w*a.w
                + b.x*b.x + b.y*b.y + b.z*b.z + b.w*b.w;
        #pragma unroll
        for (int off = 16; off > 0; off >>= 1) p += __shfl_xor_sync(FULLM, p, off);
        if (lane == 0) s_xn[row] = p;
    }

    // ---- stage chunk 0 ----
    {
        #pragma unroll
        for (int it = 0; it < 4; ++it) {
            int fidx = it * 256 + tid;           // 0..1023
            int mm = fidx >> 2, dc4 = fidx & 3;
            float4 v = *(const float4*)&W[mm * 256 + /*c=0*/ dc4 * 4];
            ws[0][(dc4 * 4 + 0) * 260 + mm] = v.x;
            ws[0][(dc4 * 4 + 1) * 260 + mm] = v.y;
            ws[0][(dc4 * 4 + 2) * 260 + mm] = v.z;
            ws[0][(dc4 * 4 + 3) * 260 + mm] = v.w;
        }
    }
    __syncthreads();

    unsigned long long acc[4][4];
    #pragma unroll
    for (int r = 0; r < 4; ++r)
        #pragma unroll
        for (int q = 0; q < 4; ++q) acc[r][q] = 0ull;

    #pragma unroll 1
    for (int c = 0; c < 16; ++c) {
        const int b = c & 1;
        // prefetch next chunk into registers (LDG latency hidden by compute)
        float4 pre[4];
        if (c < 15) {
            #pragma unroll
            for (int it = 0; it < 4; ++it) {
                int fidx = it * 256 + tid;
                int mm = fidx >> 2, dc4 = fidx & 3;
                pre[it] = *(const float4*)&W[mm * 256 + (c + 1) * 16 + dc4 * 4];
            }
        }

        // compute chunk c from ws[b]
        const float* wsb = ws[b];
        #pragma unroll
        for (int kq = 0; kq < 4; ++kq) {
            float4 xr[4];
            #pragma unroll
            for (int r = 0; r < 4; ++r)
                xr[r] = *(const float4*)&xs[(ty * 4 + r) * 256 + c * 16 + kq * 4];
            #pragma unroll
            for (int k2 = 0; k2 < 4; ++k2) {
                const int kc = kq * 4 + k2;
                ulonglong2 wA = *(const ulonglong2*)&wsb[kc * 260 + tx * 4];
                ulonglong2 wB = *(const ulonglong2*)&wsb[kc * 260 + 128 + tx * 4];
                #pragma unroll
                for (int r = 0; r < 4; ++r) {
                    float xv = (k2 == 0) ? xr[r].x : (k2 == 1) ? xr[r].y
                             : (k2 == 2) ? xr[r].z : xr[r].w;
                    unsigned long long xx = pack2(xv);
                    acc[r][0] = ffma2(xx, wA.x, acc[r][0]);
                    acc[r][1] = ffma2(xx, wA.y, acc[r][1]);
                    acc[r][2] = ffma2(xx, wB.x, acc[r][2]);
                    acc[r][3] = ffma2(xx, wB.y, acc[r][3]);
                }
            }
        }

        // stage next chunk into the other buffer
        if (c < 15) {
            float* wsn = ws[1 - b];
            #pragma unroll
            for (int it = 0; it < 4; ++it) {
                int fidx = it * 256 + tid;
                int mm = fidx >> 2, dc4 = fidx & 3;
                wsn[(dc4 * 4 + 0) * 260 + mm] = pre[it].x;
                wsn[(dc4 * 4 + 1) * 260 + mm] = pre[it].y;
                wsn[(dc4 * 4 + 2) * 260 + mm] = pre[it].z;
                wsn[(dc4 * 4 + 3) * 260 + mm] = pre[it].w;
            }
            __syncthreads();
        }
    }

    // ---- epilogue ----
    #pragma unroll
    for (int r = 0; r < 4; ++r) {
        int row = r0 + ty * 4 + r;
        float xr = s_xn[ty * 4 + r];
        float2 a0 = unpack2(acc[r][0]), a1 = unpack2(acc[r][1]);
        float2 a2 = unpack2(acc[r][2]), a3 = unpack2(acc[r][3]);
        float4 dA, dB;
        dA.x = fmaxf(xr + s_wsq[tx * 4 + 0]       - 2.0f * a0.x, 0.0f);
        dA.y = fmaxf(xr + s_wsq[tx * 4 + 1]       - 2.0f * a0.y, 0.0f);
        dA.z = fmaxf(xr + s_wsq[tx * 4 + 2]       - 2.0f * a1.x, 0.0f);
        dA.w = fmaxf(xr + s_wsq[tx * 4 + 3]       - 2.0f * a1.y, 0.0f);
        dB.x = fmaxf(xr + s_wsq[128 + tx * 4 + 0] - 2.0f * a2.x, 0.0f);
        dB.y = fmaxf(xr + s_wsq[128 + tx * 4 + 1] - 2.0f * a2.y, 0.0f);
        dB.z = fmaxf(xr + s_wsq[128 + tx * 4 + 2] - 2.0f * a3.x, 0.0f);
        dB.w = fmaxf(xr + s_wsq[128 + tx * 4 + 3] - 2.0f * a3.y, 0.0f);
        if (!proto) {
            dA.x = sqrtf(dA.x); dA.y = sqrtf(dA.y); dA.z = sqrtf(dA.z); dA.w = sqrtf(dA.w);
            dB.x = sqrtf(dB.x); dB.y = sqrtf(dB.y); dB.z = sqrtf(dB.z); dB.w = sqrtf(dB.w);
            *(float4*)&g_dist[row * M_N + tx * 4]       = dA;
            *(float4*)&g_dist[row * M_N + 128 + tx * 4] = dB;
        } else {
            *(float4*)&g_protosq[row * M_N + tx * 4]       = dA;
            *(float4*)&g_protosq[row * M_N + 128 + tx * 4] = dB;
        }
    }
}

// ---------------- edge graph terms ----------------
__global__ __launch_bounds__(256) void k_edge(const float* __restrict__ E) {
    __shared__ float red[256];
    const int i = blockIdx.x;
    const int j = threadIdx.x;

    float z = 0.5f * (E[i * M_N + j] + E[j * M_N + i]);
    float p = 0.0f;
    if (j != i) p = 1.0f / (1.0f + __expf(-z));
    float pd = p * g_protosq[i * M_N + j];

    float sp  = block_reduce_256(p, red);
    float spd = block_reduce_256(pd, red);

    if (j == 0) {
        g_rowp[i]   = sp;
        g_rowpd[i]  = spd;
        g_factor[i] = 1.0f + TOPO_F * sp / (float)(M_N - 1);
    }
}

// ---------------- off-diagonal tile pair with antisymmetric reuse ------
__device__ __forceinline__ void tilepair(const unsigned* dup, unsigned di2, int lane,
                                         int J, int slot, float& sx, float& sy,
                                         float2* part) {
    const unsigned* tj = dup + J * 64;
    float sjx = 0.0f, sjy = 0.0f;
    #pragma unroll
    for (int kg = 0; kg < 8; ++kg) {
        unsigned sacc = 0u, racc = 0u;
        #pragma unroll
        for (int q = 0; q < 4; ++q) {
            const int k = kg * 4 + q;
            unsigned dj = tj[lane ^ k];
            unsigned t  = h2tanh(h2sub(di2, dj));
            unsigned r  = __shfl_xor_sync(FULLM, t, k);
            sacc = h2add(sacc, t);
            racc = h2add(racc, r);
        }
        h2acc(sacc, sx, sy);        // si += sum t
        h2accneg(racc, sjx, sjy);   // sj -= sum r
    }
    part[(J * 4 + slot) * 32 + lane] = make_float2(sjx, sjy);
}

// ---------------- rank: halved f16x2 tanh + fused final ----------------
__global__ __launch_bounds__(256) void k_rank2(float* __restrict__ out) {
    __shared__ __align__(16) unsigned dup[8 * 64];   // per-tile duplicated half2 dists
    __shared__ float2 part[8 * 4 * 32];
    __shared__ float redx[256];
    __shared__ float redy[256];
    __shared__ bool amLast;

    const int tid  = threadIdx.x;
    const int lane = tid & 31;
    const int w    = tid >> 5;
    const int p    = blockIdx.x;

    float d0  = g_dist[(2 * p + 0) * M_N + tid];
    float d1  = g_dist[(2 * p + 1) * M_N + tid];
    float fac = g_factor[tid];

    // exact fp32 row means (for fp16 centering)
    redx[tid] = d0; redy[tid] = d1;
    __syncthreads();
    #pragma unroll
    for (int s = 128; s > 0; s >>= 1) {
        if (tid < s) { redx[tid] += redx[tid + s]; redy[tid] += redy[tid + s]; }
        __syncthreads();
    }
    float m0 = redx[0] * (1.0f / 256.0f);
    float m1 = redy[0] * (1.0f / 256.0f);
    __syncthreads();

    __half2 hc = __floats2half2_rn((d0 - m0) * INV2TAU_F, (d1 - m1) * INV2TAU_F);
    unsigned hcu = *reinterpret_cast<unsigned*>(&hc);
    dup[w * 64 + lane]      = hcu;
    dup[w * 64 + 32 + lane] = hcu;
    __syncthreads();

    const unsigned di2 = dup[w * 64 + lane];
    float sx = 0.0f, sy = 0.0f;

    // ---- diagonal tile: rotation k=1..15 with reuse, k=16 unhalved ----
    {
        const unsigned* tw = dup + w * 64;
        unsigned sacc = 0u, racc = 0u;
        #pragma unroll
        for (int k = 1; k <= 15; ++k) {
            unsigned dj = tw[lane + k];
            unsigned t  = h2tanh(h2sub(di2, dj));
            unsigned r  = __shfl_sync(FULLM, t, (lane - k) & 31);
            sacc = h2add(sacc, t);
            racc = h2add(racc, r);
            if ((k & 3) == 0 || k == 15) {
                h2acc(sacc, sx, sy);
                h2accneg(racc, sx, sy);
                sacc = 0u; racc = 0u;
            }
        }
        unsigned dj = tw[lane + 16];
        unsigned t  = h2tanh(h2sub(di2, dj));
        h2acc(t, sx, sy);
    }

    // ---- off-diagonal tile pairs (each unordered pair once) ----
    tilepair(dup, di2, lane, (w + 1) & 7, 0, sx, sy, part);
    tilepair(dup, di2, lane, (w + 2) & 7, 1, sx, sy, part);
    tilepair(dup, di2, lane, (w + 3) & 7, 2, sx, sy, part);
    if (w < 4) tilepair(dup, di2, lane, w + 4, 3, sx, sy, part);
    __syncthreads();

    {
        float2 q0 = part[(w * 4 + 0) * 32 + lane];
        float2 q1 = part[(w * 4 + 1) * 32 + lane];
        float2 q2 = part[(w * 4 + 2) * 32 + lane];
        sx += q0.x + q1.x + q2.x;
        sy += q0.y + q1.y + q2.y;
        if (w >= 4) {
            float2 q3 = part[(w * 4 + 3) * 32 + lane];
            sx += q3.x; sy += q3.y;
        }
    }

    float srm0 = 127.5f + 0.5f * sx;
    float srm1 = 127.5f + 0.5f * sy;
    float contrib = exp2f(srm0 * NEIGH_LOG2) * fac * d0
                  + exp2f(srm1 * NEIGH_LOG2) * fac * d1;

    float s = block_reduce_256(contrib, redx);
    if (tid == 0) g_partial[p] = s;

    // ---- last block computes the final scalar ----
    if (tid == 0) {
        __threadfence();
        amLast = (atomicAdd(&g_ctr, 1) == NPAIR - 1);
    }
    __syncthreads();
    if (amLast) {
        float acc = 0.0f;
        #pragma unroll
        for (int i = tid; i < NPAIR; i += 256) acc += g_partial[i];
        float data_sum = block_reduce_256(acc, redx);
        float sp  = block_reduce_256(g_rowp[tid],  redx);
        float spd = block_reduce_256(g_rowpd[tid], redx);
        if (tid == 0) {
            float data_term = data_sum / ((float)B_N * (float)M_N);
            float wlen      = spd / (sp + 1e-8f);
            float sparsity  = sp / ((float)M_N * (float)M_N);
            out[0] = data_term + LEN_C_F * wlen + SP_C_F * sparsity;
        }
    }
}

// ---------------- launch ----------------
extern "C" void kernel_launch(void* const* d_in, const int* in_sizes, int n_in,
                              void* d_out, int out_size) {
    const float* data = (const float*)d_in[0];   // [4096, 256]
    const float* w    = (const float*)d_in[1];   // [256, 256]
    const float* E    = (const float*)d_in[2];   // [256, 256]
    float* out = (float*)d_out;

    k_gemm  <<<136, 256>>>(data, w);   // data dists + proto sq dists + ctr reset
    k_edge  <<<M_N, 256>>>(E);
    k_rank2 <<<NPAIR, 256>>>(out);
}